// round 4
// baseline (speedup 1.0000x reference)
#include <cuda_runtime.h>

// Problem constants
#define BB   4
#define SS   2048
#define MM   4096
#define DD   512
#define MLPD 1024

// d_out = out [B,S,512] (4,194,304 floats) followed by attn [B,S,M] (33,554,432 floats)
#define OUT_ELEMS  (BB*SS*DD)

// Scratch (static __device__ arrays: allocation-free per harness rules)
__device__ float g_Q   [BB*SS*DD];    // 16.8 MB
__device__ float g_K   [BB*MM*DD];    // 33.6 MB
__device__ float g_V   [BB*MM*DD];    // 33.6 MB
__device__ float g_Vbar[BB*SS*DD];    // 16.8 MB
__device__ float g_H   [BB*SS*MLPD];  // 33.6 MB

// ---------------------------------------------------------------------------
// Tiled SGEMM, double-buffered smem pipeline:
//   C = op(A,B)*scale (+bias) (+relu)
//   TRANSB=false: C[M,N] = A[M,K] @ B[K,N]       (B row-major [K,N])
//   TRANSB=true : C[M,N] = A[M,K] @ B^T          (B row-major [N,K])
// BM=BN=128, BK=16, 256 threads, 8x8 microtile. All dims divide tile sizes.
// blockIdx.z batches with strides sA/sB/sC.
// ---------------------------------------------------------------------------
template<bool TRANSB, bool RELU, bool BIAS>
__global__ void __launch_bounds__(256, 2)
sgemm128(const float* __restrict__ Ag, const float* __restrict__ Bg,
         const float* __restrict__ bias, float* __restrict__ Cg,
         int M, int N, int K,
         long long sA, long long sB, long long sC, float scale)
{
    constexpr int BM = 128, BN = 128, BK = 16;
    __shared__ float As[2][BK][BM];
    __shared__ float Bs[2][BK][BN];

    const float* A = Ag + (long long)blockIdx.z * sA;
    const float* B = Bg + (long long)blockIdx.z * sB;
    float*       C = Cg + (long long)blockIdx.z * sC;

    const int tid  = threadIdx.x;
    const int tx   = tid & 15;        // 0..15 -> N micro
    const int ty   = tid >> 4;        // 0..15 -> M micro
    const int row0 = blockIdx.y * BM;
    const int col0 = blockIdx.x * BN;

    float acc[8][8];
#pragma unroll
    for (int i = 0; i < 8; i++)
#pragma unroll
        for (int j = 0; j < 8; j++) acc[i][j] = 0.f;

    // A-tile load mapping: 128 rows x 16 cols = 512 float4 slots, 2 per thread
    const int aRow = tid >> 2;          // 0..63 (+64)
    const int aCol = (tid & 3) * 4;     // {0,4,8,12}
    // B-tile (no-trans): 16 k-rows x 128 cols
    const int bRowN = tid >> 5;         // 0..7 (+8)
    const int bColN = (tid & 31) * 4;   // 0..124
    // B-tile (trans): 128 n-rows x 16 k-cols
    const int bRowT = tid >> 2;         // 0..63 (+64)
    const int bColT = (tid & 3) * 4;

    const int nIter = K / BK;

    float4 ra[2], rb[2];

    // ---- fetch tile k0 into registers ----
    auto fetch = [&](int k0) {
#pragma unroll
        for (int r = 0; r < 2; r++)
            ra[r] = *(const float4*)(A + (long long)(row0 + aRow + r * 64) * K + k0 + aCol);
        if (!TRANSB) {
#pragma unroll
            for (int r = 0; r < 2; r++)
                rb[r] = *(const float4*)(B + (long long)(k0 + bRowN + r * 8) * N + col0 + bColN);
        } else {
#pragma unroll
            for (int r = 0; r < 2; r++)
                rb[r] = *(const float4*)(B + (long long)(col0 + bRowT + r * 64) * K + k0 + bColT);
        }
    };

    // ---- store registers into smem buffer bf ----
    auto stage = [&](int bf) {
#pragma unroll
        for (int r = 0; r < 2; r++) {
            const int rr = aRow + r * 64;
            As[bf][aCol + 0][rr] = ra[r].x;
            As[bf][aCol + 1][rr] = ra[r].y;
            As[bf][aCol + 2][rr] = ra[r].z;
            As[bf][aCol + 3][rr] = ra[r].w;
        }
        if (!TRANSB) {
#pragma unroll
            for (int r = 0; r < 2; r++)
                *(float4*)&Bs[bf][bRowN + r * 8][bColN] = rb[r];
        } else {
#pragma unroll
            for (int r = 0; r < 2; r++) {
                const int nn = bRowT + r * 64;
                Bs[bf][bColT + 0][nn] = rb[r].x;
                Bs[bf][bColT + 1][nn] = rb[r].y;
                Bs[bf][bColT + 2][nn] = rb[r].z;
                Bs[bf][bColT + 3][nn] = rb[r].w;
            }
        }
    };

    // prologue: tile 0 -> smem buffer 0
    fetch(0);
    stage(0);
    __syncthreads();

    for (int it = 0; it < nIter; it++) {
        const int cur = it & 1;

        // prefetch next tile into registers (latency hidden under FMAs below)
        if (it + 1 < nIter) fetch((it + 1) * BK);

        // compute on current buffer
#pragma unroll
        for (int kk = 0; kk < BK; kk++) {
            float a[8], b[8];
            *(float4*)&a[0] = *(const float4*)&As[cur][kk][ty * 8];
            *(float4*)&a[4] = *(const float4*)&As[cur][kk][ty * 8 + 4];
            *(float4*)&b[0] = *(const float4*)&Bs[cur][kk][tx * 8];
            *(float4*)&b[4] = *(const float4*)&Bs[cur][kk][tx * 8 + 4];
#pragma unroll
            for (int i = 0; i < 8; i++)
#pragma unroll
                for (int j = 0; j < 8; j++)
                    acc[i][j] += a[i] * b[j];
        }

        if (it + 1 < nIter) {
            stage(1 - cur);        // write buffer other warps finished last iter
            __syncthreads();
        }
    }

    // epilogue
#pragma unroll
    for (int i = 0; i < 8; i++) {
        const long long r = row0 + ty * 8 + i;
        float* crow = C + r * (long long)N + col0 + tx * 8;
#pragma unroll
        for (int j0 = 0; j0 < 8; j0 += 4) {
            float4 v;
            v.x = acc[i][j0 + 0] * scale;
            v.y = acc[i][j0 + 1] * scale;
            v.z = acc[i][j0 + 2] * scale;
            v.w = acc[i][j0 + 3] * scale;
            if (BIAS) {
                const int c = col0 + tx * 8 + j0;
                v.x += bias[c + 0]; v.y += bias[c + 1];
                v.z += bias[c + 2]; v.w += bias[c + 3];
            }
            if (RELU) {
                v.x = fmaxf(v.x, 0.f); v.y = fmaxf(v.y, 0.f);
                v.z = fmaxf(v.z, 0.f); v.w = fmaxf(v.w, 0.f);
            }
            *(float4*)(crow + j0) = v;
        }
    }
}

// ---------------------------------------------------------------------------
// Row softmax over M=4096, one block (256 threads) per row, values live in
// registers (16 per thread): single gmem read + single write.
// ---------------------------------------------------------------------------
__global__ void __launch_bounds__(256)
softmax4096(float* __restrict__ attn)
{
    __shared__ float red[32];
    float* p = attn + (long long)blockIdx.x * MM;
    const int tid = threadIdx.x;

    float v[16];
    float mx = -3.0e38f;
#pragma unroll
    for (int i = 0; i < 16; i++) {
        v[i] = p[tid + i * 256];
        mx = fmaxf(mx, v[i]);
    }
#pragma unroll
    for (int o = 16; o > 0; o >>= 1) mx = fmaxf(mx, __shfl_xor_sync(0xffffffffu, mx, o));
    if ((tid & 31) == 0) red[tid >> 5] = mx;
    __syncthreads();
    if (tid < 32) {
        float t = (tid < 8) ? red[tid] : -3.0e38f;
#pragma unroll
        for (int o = 4; o > 0; o >>= 1) t = fmaxf(t, __shfl_xor_sync(0xffffffffu, t, o));
        if (tid == 0) red[0] = t;
    }
    __syncthreads();
    mx = red[0];
    __syncthreads();

    float s = 0.f;
#pragma unroll
    for (int i = 0; i < 16; i++) {
        v[i] = expf(v[i] - mx);
        s += v[i];
    }
#pragma unroll
    for (int o = 16; o > 0; o >>= 1) s += __shfl_xor_sync(0xffffffffu, s, o);
    if ((tid & 31) == 0) red[tid >> 5] = s;
    __syncthreads();
    if (tid < 32) {
        float t = (tid < 8) ? red[tid] : 0.f;
#pragma unroll
        for (int o = 4; o > 0; o >>= 1) t += __shfl_xor_sync(0xffffffffu, t, o);
        if (tid == 0) red[0] = t;
    }
    __syncthreads();
    const float inv = 1.0f / red[0];

#pragma unroll
    for (int i = 0; i < 16; i++)
        p[tid + i * 256] = v[i] * inv;
}

// ---------------------------------------------------------------------------
extern "C" void kernel_launch(void* const* d_in, const int* in_sizes, int n_in,
                              void* d_out, int out_size)
{
    (void)in_sizes; (void)n_in; (void)out_size;
    const float* x  = (const float*)d_in[0];
    const float* m  = (const float*)d_in[1];
    const float* Wq = (const float*)d_in[2];
    const float* bq = (const float*)d_in[3];
    const float* Wk = (const float*)d_in[4];
    const float* bk = (const float*)d_in[5];
    const float* Wv = (const float*)d_in[6];
    const float* bv = (const float*)d_in[7];
    const float* W1 = (const float*)d_in[8];
    const float* b1 = (const float*)d_in[9];
    const float* W2 = (const float*)d_in[10];
    const float* b2 = (const float*)d_in[11];

    float* out  = (float*)d_out;               // [B*S, 512]
    float* attn = (float*)d_out + OUT_ELEMS;   // [B, S, M]

    float *pQ, *pK, *pV, *pVb, *pH;
    cudaGetSymbolAddress((void**)&pQ,  g_Q);
    cudaGetSymbolAddress((void**)&pK,  g_K);
    cudaGetSymbolAddress((void**)&pV,  g_V);
    cudaGetSymbolAddress((void**)&pVb, g_Vbar);
    cudaGetSymbolAddress((void**)&pH,  g_H);

    const float scale = 0.044194173824159216f;  // 1/sqrt(512)

    // Q = x @ Wq + bq : [8192,512]
    sgemm128<false,false,true><<<dim3(DD/128, (BB*SS)/128, 1), 256>>>(
        x, Wq, bq, pQ, BB*SS, DD, DD, 0, 0, 0, 1.0f);
    // K = m @ Wk + bk : [16384,512]
    sgemm128<false,false,true><<<dim3(DD/128, (BB*MM)/128, 1), 256>>>(
        m, Wk, bk, pK, BB*MM, DD, DD, 0, 0, 0, 1.0f);
    // V = m @ Wv + bv
    sgemm128<false,false,true><<<dim3(DD/128, (BB*MM)/128, 1), 256>>>(
        m, Wv, bv, pV, BB*MM, DD, DD, 0, 0, 0, 1.0f);

    // logits = scale * Q @ K^T per batch : [2048,4096], K=512
    sgemm128<true,false,false><<<dim3(MM/128, SS/128, BB), 256>>>(
        pQ, pK, nullptr, attn, SS, MM, DD,
        (long long)SS*DD, (long long)MM*DD, (long long)SS*MM, scale);

    // softmax rows (in-place in d_out attn region)
    softmax4096<<<BB*SS, 256>>>(attn);

    // V_bar = attn @ V per batch : [2048,512], K=4096
    sgemm128<false,false,false><<<dim3(DD/128, SS/128, BB), 256>>>(
        attn, pV, nullptr, pVb, SS, DD, MM,
        (long long)SS*MM, (long long)MM*DD, (long long)SS*DD, 1.0f);

    // h = relu(V_bar @ W1 + b1) : [8192,1024]
    sgemm128<false,true,true><<<dim3(MLPD/128, (BB*SS)/128, 1), 256>>>(
        pVb, W1, b1, pH, BB*SS, MLPD, DD, 0, 0, 0, 1.0f);

    // out = h @ W2 + b2 : [8192,512]
    sgemm128<false,false,true><<<dim3(DD/128, (BB*SS)/128, 1), 256>>>(
        pH, W2, b2, out, BB*SS, DD, MLPD, 0, 0, 0, 1.0f);
}

// round 9
// speedup vs baseline: 2.6209x; 2.6209x over previous
#include <cuda_runtime.h>
#include <cuda_bf16.h>
#include <cstdint>

// ---------------------------------------------------------------------------
// Problem constants
// ---------------------------------------------------------------------------
#define BB   4
#define SS   2048
#define MM   4096
#define DD   512
#define MLPD 1024
#define OUT_ELEMS (BB*SS*DD)

// ---------------------------------------------------------------------------
// Scratch (__device__ globals: allocation-free per harness rules)
// ---------------------------------------------------------------------------
__device__ __nv_bfloat16 g_xhi [BB*SS*DD],  g_xlo [BB*SS*DD];
__device__ __nv_bfloat16 g_mhi [BB*MM*DD],  g_mlo [BB*MM*DD];
__device__ __nv_bfloat16 g_WqThi[DD*DD],    g_WqTlo[DD*DD];
__device__ __nv_bfloat16 g_WkThi[DD*DD],    g_WkTlo[DD*DD];
__device__ __nv_bfloat16 g_WvThi[DD*DD],    g_WvTlo[DD*DD];
__device__ __nv_bfloat16 g_W1Thi[MLPD*DD],  g_W1Tlo[MLPD*DD];
__device__ __nv_bfloat16 g_W2Thi[DD*MLPD],  g_W2Tlo[DD*MLPD];
__device__ __nv_bfloat16 g_Qhi [BB*SS*DD],  g_Qlo [BB*SS*DD];
__device__ __nv_bfloat16 g_Khi [BB*MM*DD],  g_Klo [BB*MM*DD];
__device__ float         g_V   [BB*MM*DD];
__device__ __nv_bfloat16 g_Vthi[BB*DD*MM],  g_Vtlo[BB*DD*MM];
__device__ __nv_bfloat16 g_Phi [BB*SS*MM],  g_Plo [BB*SS*MM];
__device__ __nv_bfloat16 g_Vbhi[BB*SS*DD],  g_Vblo[BB*SS*DD];
__device__ __nv_bfloat16 g_Hhi [BB*SS*MLPD],g_Hlo [BB*SS*MLPD];

// ---------------------------------------------------------------------------
// PTX helpers (baseline sm_80+ features only: ldmatrix / mma.sync / cp.async)
// ---------------------------------------------------------------------------
__device__ __forceinline__ uint32_t smem_u32(const void* p) {
    uint32_t a;
    asm("{ .reg .u64 t; cvta.to.shared.u64 t, %1; cvt.u32.u64 %0, t; }" : "=r"(a) : "l"(p));
    return a;
}
__device__ __forceinline__ void ldsm4(uint32_t* r, uint32_t a) {
    asm volatile("ldmatrix.sync.aligned.m8n8.x4.shared.b16 {%0,%1,%2,%3}, [%4];"
        : "=r"(r[0]), "=r"(r[1]), "=r"(r[2]), "=r"(r[3]) : "r"(a));
}
__device__ __forceinline__ void mma16816(float* c, const uint32_t* a, const uint32_t* b) {
    asm volatile("mma.sync.aligned.m16n8k16.row.col.f32.bf16.bf16.f32 "
        "{%0,%1,%2,%3}, {%4,%5,%6,%7}, {%8,%9}, {%0,%1,%2,%3};"
        : "+f"(c[0]), "+f"(c[1]), "+f"(c[2]), "+f"(c[3])
        : "r"(a[0]), "r"(a[1]), "r"(a[2]), "r"(a[3]), "r"(b[0]), "r"(b[1]));
}
#define CPASYNC16(smaddr, gptr) \
    asm volatile("cp.async.cg.shared.global [%0], [%1], 16;" :: "r"(smaddr), "l"(gptr))
#define CP_COMMIT()  asm volatile("cp.async.commit_group;" ::: "memory")
#define CP_WAIT1()   asm volatile("cp.async.wait_group 1;" ::: "memory")

__device__ __forceinline__ uint32_t pack_bf2(float a, float b) {
    __nv_bfloat16 h0 = __float2bfloat16(a);
    __nv_bfloat16 h1 = __float2bfloat16(b);
    return (uint32_t)__bfloat16_as_ushort(h0) | ((uint32_t)__bfloat16_as_ushort(h1) << 16);
}

// ---------------------------------------------------------------------------
// mma.sync GEMM: C[M,N] = scale * (A @ B^T) (+bias) (+relu)
//   A: hi/lo bf16 [M,K] row-major; B: hi/lo bf16 [N,K] row-major (K-major).
//   3-term split: Ahi*Bhi + Ahi*Blo + Alo*Bhi, fp32 accumulators.
//   CTA tile 128x128, BK=32, 256 threads (8 warps, 2Mx4N -> 64x32 warp tile),
//   3-stage cp.async pipeline, XOR-swizzled smem (conflict-free ldmatrix).
//   Smem stage layout: [Ahi 8K][Alo 8K][Bhi 8K][Blo 8K] = 32KB; 3 stages.
// ---------------------------------------------------------------------------
#define HG_STAGE   32768
#define HG_SMEM    (3 * HG_STAGE)

template<bool RELU, bool BIAS, bool SPLITOUT>
__global__ void __launch_bounds__(256, 1)
hgemm(const __nv_bfloat16* __restrict__ Ahi, const __nv_bfloat16* __restrict__ Alo,
      const __nv_bfloat16* __restrict__ Bhi, const __nv_bfloat16* __restrict__ Blo,
      const float* __restrict__ bias,
      float* __restrict__ Cf,
      __nv_bfloat16* __restrict__ Chi, __nv_bfloat16* __restrict__ Clo,
      int M, int N, int K,
      long long sA, long long sB, long long sC, float scale)
{
    extern __shared__ char dsm[];
    const uint32_t smem0 = smem_u32(dsm);

    const int tid  = threadIdx.x;
    const int lane = tid & 31;
    const int wid  = tid >> 5;
    const int wm   = wid & 1;     // 0..1 -> 64-row group
    const int wn   = wid >> 1;    // 0..3 -> 32-col group
    const int row0 = blockIdx.y * 128;
    const int col0 = blockIdx.x * 128;

    const long long zA = (long long)blockIdx.z * sA;
    const long long zB = (long long)blockIdx.z * sB;
    const long long zC = (long long)blockIdx.z * sC;
    const __nv_bfloat16* pAhi = Ahi + zA;
    const __nv_bfloat16* pAlo = Alo + zA;
    const __nv_bfloat16* pBhi = Bhi + zB;
    const __nv_bfloat16* pBlo = Blo + zB;

    // gmem->smem: 128 rows x 32 bf16 per matrix; row = 4 chunks of 16B.
    // Swizzle: chunk' = chunk ^ ((row>>1)&3)  (conflict-free ldmatrix phases)
    auto load_stage = [&](int slot, int kt) {
        const int k0 = kt * 32;
        const uint32_t sb = smem0 + (uint32_t)slot * HG_STAGE;
#pragma unroll
        for (int t = 0; t < 2; ++t) {
            const int idx = tid + t * 256;       // 0..511
            const int r   = idx >> 2;            // 0..127
            const int c   = idx & 3;             // 16B chunk
            const int c2  = c ^ ((r >> 1) & 3);
            const uint32_t so = sb + (uint32_t)(r * 64 + c2 * 16);
            const long long ga = (long long)(row0 + r) * K + k0 + c * 8;
            const long long gb = (long long)(col0 + r) * K + k0 + c * 8;
            CPASYNC16(so,         pAhi + ga);
            CPASYNC16(so +  8192, pAlo + ga);
            CPASYNC16(so + 16384, pBhi + gb);
            CPASYNC16(so + 24576, pBlo + gb);
        }
    };

    float acc[4][4][4];
#pragma unroll
    for (int i = 0; i < 4; ++i)
#pragma unroll
        for (int j = 0; j < 4; ++j)
#pragma unroll
            for (int q = 0; q < 4; ++q) acc[i][j][q] = 0.f;

    // ldmatrix per-thread address components
    const int rA    = wm * 64 + (lane & 15);            // A row within tile
    const int kparA = (lane >> 4) & 1;                  // +8 k-chunk for mats 2,3
    const int rB    = wn * 32 + (lane & 7) + ((lane & 16) ? 8 : 0);
    const int kparB = (lane >> 3) & 1;

    const int nkt = K >> 5;     // K/32 (>=16 for all our shapes)

    load_stage(0, 0); CP_COMMIT();
    load_stage(1, 1); CP_COMMIT();

    for (int kt = 0; kt < nkt; ++kt) {
        CP_WAIT1();
        __syncthreads();
        if (kt + 2 < nkt) load_stage((kt + 2) % 3, kt + 2);
        CP_COMMIT();

        const uint32_t sb = smem0 + (uint32_t)(kt % 3) * HG_STAGE;
#pragma unroll
        for (int ks = 0; ks < 2; ++ks) {
            uint32_t ah[4][4], al[4][4];
#pragma unroll
            for (int mf = 0; mf < 4; ++mf) {
                const int r  = rA + mf * 16;
                const int c2 = (ks * 2 + kparA) ^ ((r >> 1) & 3);
                const uint32_t off = (uint32_t)(r * 64 + c2 * 16);
                ldsm4(ah[mf], sb + off);
                ldsm4(al[mf], sb + 8192 + off);
            }
            uint32_t bh[4][2], bl[4][2];
#pragma unroll
            for (int nb = 0; nb < 2; ++nb) {
                const int r  = rB + nb * 16;
                const int c2 = (ks * 2 + kparB) ^ ((r >> 1) & 3);
                const uint32_t off = (uint32_t)(r * 64 + c2 * 16);
                uint32_t t4[4];
                ldsm4(t4, sb + 16384 + off);
                bh[nb*2][0] = t4[0]; bh[nb*2][1] = t4[1];
                bh[nb*2+1][0] = t4[2]; bh[nb*2+1][1] = t4[3];
                ldsm4(t4, sb + 24576 + off);
                bl[nb*2][0] = t4[0]; bl[nb*2][1] = t4[1];
                bl[nb*2+1][0] = t4[2]; bl[nb*2+1][1] = t4[3];
            }
#pragma unroll
            for (int mf = 0; mf < 4; ++mf)
#pragma unroll
                for (int nf = 0; nf < 4; ++nf) {
                    mma16816(acc[mf][nf], ah[mf], bh[nf]);
                    mma16816(acc[mf][nf], ah[mf], bl[nf]);
                    mma16816(acc[mf][nf], al[mf], bh[nf]);
                }
        }
    }

    // Epilogue: d0,d1 -> (row=lane>>2, col=(lane&3)*2+{0,1}); d2,d3 -> row+8
#pragma unroll
    for (int nf = 0; nf < 4; ++nf) {
        const int col = col0 + wn * 32 + nf * 8 + (lane & 3) * 2;
        float bx = 0.f, by = 0.f;
        if (BIAS) { bx = bias[col]; by = bias[col + 1]; }
#pragma unroll
        for (int mf = 0; mf < 4; ++mf) {
            const int ra = row0 + wm * 64 + mf * 16 + (lane >> 2);
            float v0 = acc[mf][nf][0] * scale;
            float v1 = acc[mf][nf][1] * scale;
            float v2 = acc[mf][nf][2] * scale;
            float v3 = acc[mf][nf][3] * scale;
            if (BIAS) { v0 += bx; v1 += by; v2 += bx; v3 += by; }
            if (RELU) {
                v0 = fmaxf(v0, 0.f); v1 = fmaxf(v1, 0.f);
                v2 = fmaxf(v2, 0.f); v3 = fmaxf(v3, 0.f);
            }
            const long long o0 = zC + (long long)ra * N + col;
            const long long o1 = o0 + 8LL * N;
            if (SPLITOUT) {
                const __nv_bfloat16 h0 = __float2bfloat16(v0);
                const __nv_bfloat16 h1 = __float2bfloat16(v1);
                const __nv_bfloat16 h2 = __float2bfloat16(v2);
                const __nv_bfloat16 h3 = __float2bfloat16(v3);
                *(uint32_t*)(Chi + o0) =
                    (uint32_t)__bfloat16_as_ushort(h0) | ((uint32_t)__bfloat16_as_ushort(h1) << 16);
                *(uint32_t*)(Chi + o1) =
                    (uint32_t)__bfloat16_as_ushort(h2) | ((uint32_t)__bfloat16_as_ushort(h3) << 16);
                *(uint32_t*)(Clo + o0) =
                    pack_bf2(v0 - __bfloat162float(h0), v1 - __bfloat162float(h1));
                *(uint32_t*)(Clo + o1) =
                    pack_bf2(v2 - __bfloat162float(h2), v3 - __bfloat162float(h3));
            } else {
                float2 p0; p0.x = v0; p0.y = v1;
                float2 p1; p1.x = v2; p1.y = v3;
                *(float2*)(Cf + o0) = p0;
                *(float2*)(Cf + o1) = p1;
            }
        }
    }
}

// ---------------------------------------------------------------------------
// Elementwise hi/lo split: X fp32 -> Hi, Lo bf16 (float4-vectorized)
// ---------------------------------------------------------------------------
__global__ void __launch_bounds__(256)
split_kernel(const float* __restrict__ X, __nv_bfloat16* __restrict__ Hi,
             __nv_bfloat16* __restrict__ Lo, int n4)
{
    const int i = blockIdx.x * 256 + threadIdx.x;
    if (i >= n4) return;
    const float4 v = ((const float4*)X)[i];
    const __nv_bfloat16 h0 = __float2bfloat16(v.x), h1 = __float2bfloat16(v.y);
    const __nv_bfloat16 h2 = __float2bfloat16(v.z), h3 = __float2bfloat16(v.w);
    uint2 ph, pl;
    ph.x = (uint32_t)__bfloat16_as_ushort(h0) | ((uint32_t)__bfloat16_as_ushort(h1) << 16);
    ph.y = (uint32_t)__bfloat16_as_ushort(h2) | ((uint32_t)__bfloat16_as_ushort(h3) << 16);
    pl.x = pack_bf2(v.x - __bfloat162float(h0), v.y - __bfloat162float(h1));
    pl.y = pack_bf2(v.z - __bfloat162float(h2), v.w - __bfloat162float(h3));
    ((uint2*)Hi)[i] = ph;
    ((uint2*)Lo)[i] = pl;
}

// ---------------------------------------------------------------------------
// Transpose + split: X[R,C] fp32 -> T{hi,lo}[C,R] bf16 (32x32 smem tiles)
// ---------------------------------------------------------------------------
__global__ void __launch_bounds__(256)
tsplit_kernel(const float* __restrict__ X, __nv_bfloat16* __restrict__ Thi,
              __nv_bfloat16* __restrict__ Tlo, int R, int C,
              long long sIn, long long sOut)
{
    __shared__ float t[32][33];
    const int tx = threadIdx.x, ty = threadIdx.y;   // 32 x 8
    const int c0 = blockIdx.x * 32, r0 = blockIdx.y * 32;
    const float* Xb = X + (long long)blockIdx.z * sIn;
#pragma unroll
    for (int k = 0; k < 4; ++k)
        t[ty + k*8][tx] = Xb[(long long)(r0 + ty + k*8) * C + c0 + tx];
    __syncthreads();
    const long long ob = (long long)blockIdx.z * sOut;
#pragma unroll
    for (int k = 0; k < 4; ++k) {
        const int oc   = r0 + tx;          // output fast dim (R index)
        const int orow = c0 + ty + k*8;    // output row (C index)
        const float v = t[tx][ty + k*8];
        const __nv_bfloat16 h = __float2bfloat16(v);
        Thi[ob + (long long)orow * R + oc] = h;
        Tlo[ob + (long long)orow * R + oc] = __float2bfloat16(v - __bfloat162float(h));
    }
}

// ---------------------------------------------------------------------------
// Row softmax over M=4096 (in-place fp32) + emit split-bf16 probabilities
// ---------------------------------------------------------------------------
__global__ void __launch_bounds__(256)
softmax_split(float* __restrict__ attn, __nv_bfloat16* __restrict__ Phi,
              __nv_bfloat16* __restrict__ Plo)
{
    __shared__ float red[32];
    const long long rbase = (long long)blockIdx.x * MM;
    float* p = attn + rbase;
    const int tid = threadIdx.x;

    float v[16];
    float mx = -3.0e38f;
#pragma unroll
    for (int i = 0; i < 16; i++) { v[i] = p[tid + i*256]; mx = fmaxf(mx, v[i]); }
#pragma unroll
    for (int o = 16; o > 0; o >>= 1) mx = fmaxf(mx, __shfl_xor_sync(0xffffffffu, mx, o));
    if ((tid & 31) == 0) red[tid >> 5] = mx;
    __syncthreads();
    if (tid < 32) {
        float t = (tid < 8) ? red[tid] : -3.0e38f;
#pragma unroll
        for (int o = 4; o > 0; o >>= 1) t = fmaxf(t, __shfl_xor_sync(0xffffffffu, t, o));
        if (tid == 0) red[0] = t;
    }
    __syncthreads();
    mx = red[0];
    __syncthreads();

    float s = 0.f;
#pragma unroll
    for (int i = 0; i < 16; i++) { v[i] = expf(v[i] - mx); s += v[i]; }
#pragma unroll
    for (int o = 16; o > 0; o >>= 1) s += __shfl_xor_sync(0xffffffffu, s, o);
    if ((tid & 31) == 0) red[tid >> 5] = s;
    __syncthreads();
    if (tid < 32) {
        float t = (tid < 8) ? red[tid] : 0.f;
#pragma unroll
        for (int o = 4; o > 0; o >>= 1) t += __shfl_xor_sync(0xffffffffu, t, o);
        if (tid == 0) red[0] = t;
    }
    __syncthreads();
    const float inv = 1.0f / red[0];

#pragma unroll
    for (int i = 0; i < 16; i++) {
        const float pv = v[i] * inv;
        const int idx = tid + i * 256;
        p[idx] = pv;
        const __nv_bfloat16 h = __float2bfloat16(pv);
        Phi[rbase + idx] = h;
        Plo[rbase + idx] = __float2bfloat16(pv - __bfloat162float(h));
    }
}

// ---------------------------------------------------------------------------
extern "C" void kernel_launch(void* const* d_in, const int* in_sizes, int n_in,
                              void* d_out, int out_size)
{
    (void)in_sizes; (void)n_in; (void)out_size;
    const float* x  = (const float*)d_in[0];
    const float* m  = (const float*)d_in[1];
    const float* Wq = (const float*)d_in[2];
    const float* bq = (const float*)d_in[3];
    const float* Wk = (const float*)d_in[4];
    const float* bk = (const float*)d_in[5];
    const float* Wv = (const float*)d_in[6];
    const float* bv = (const float*)d_in[7];
    const float* W1 = (const float*)d_in[8];
    const float* b1 = (const float*)d_in[9];
    const float* W2 = (const float*)d_in[10];
    const float* b2 = (const float*)d_in[11];

    float* out  = (float*)d_out;               // [B*S, 512]
    float* attn = (float*)d_out + OUT_ELEMS;   // [B, S, M]

    __nv_bfloat16 *xhi,*xlo,*mhi,*mlo,*WqThi,*WqTlo,*WkThi,*WkTlo,*WvThi,*WvTlo;
    __nv_bfloat16 *W1Thi,*W1Tlo,*W2Thi,*W2Tlo,*Qhi,*Qlo,*Khi,*Klo,*Vthi,*Vtlo;
    __nv_bfloat16 *Phi,*Plo,*Vbhi,*Vblo,*Hhi,*Hlo;
    float* Vf;
    cudaGetSymbolAddress((void**)&xhi, g_xhi);   cudaGetSymbolAddress((void**)&xlo, g_xlo);
    cudaGetSymbolAddress((void**)&mhi, g_mhi);   cudaGetSymbolAddress((void**)&mlo, g_mlo);
    cudaGetSymbolAddress((void**)&WqThi, g_WqThi); cudaGetSymbolAddress((void**)&WqTlo, g_WqTlo);
    cudaGetSymbolAddress((void**)&WkThi, g_WkThi); cudaGetSymbolAddress((void**)&WkTlo, g_WkTlo);
    cudaGetSymbolAddress((void**)&WvThi, g_WvThi); cudaGetSymbolAddress((void**)&WvTlo, g_WvTlo);
    cudaGetSymbolAddress((void**)&W1Thi, g_W1Thi); cudaGetSymbolAddress((void**)&W1Tlo, g_W1Tlo);
    cudaGetSymbolAddress((void**)&W2Thi, g_W2Thi); cudaGetSymbolAddress((void**)&W2Tlo, g_W2Tlo);
    cudaGetSymbolAddress((void**)&Qhi, g_Qhi);   cudaGetSymbolAddress((void**)&Qlo, g_Qlo);
    cudaGetSymbolAddress((void**)&Khi, g_Khi);   cudaGetSymbolAddress((void**)&Klo, g_Klo);
    cudaGetSymbolAddress((void**)&Vf,  g_V);
    cudaGetSymbolAddress((void**)&Vthi, g_Vthi); cudaGetSymbolAddress((void**)&Vtlo, g_Vtlo);
    cudaGetSymbolAddress((void**)&Phi, g_Phi);   cudaGetSymbolAddress((void**)&Plo, g_Plo);
    cudaGetSymbolAddress((void**)&Vbhi, g_Vbhi); cudaGetSymbolAddress((void**)&Vblo, g_Vblo);
    cudaGetSymbolAddress((void**)&Hhi, g_Hhi);   cudaGetSymbolAddress((void**)&Hlo, g_Hlo);

    // Opt in to 96KB dynamic smem for all hgemm instantiations
    cudaFuncSetAttribute(hgemm<false,true ,true >, cudaFuncAttributeMaxDynamicSharedMemorySize, HG_SMEM);
    cudaFuncSetAttribute(hgemm<false,true ,false>, cudaFuncAttributeMaxDynamicSharedMemorySize, HG_SMEM);
    cudaFuncSetAttribute(hgemm<false,false,false>, cudaFuncAttributeMaxDynamicSharedMemorySize, HG_SMEM);
    cudaFuncSetAttribute(hgemm<false,false,true >, cudaFuncAttributeMaxDynamicSharedMemorySize, HG_SMEM);
    cudaFuncSetAttribute(hgemm<true ,true ,true >, cudaFuncAttributeMaxDynamicSharedMemorySize, HG_SMEM);

    const float scale = 0.044194173824159216f;  // 1/sqrt(512)

    // ---- input splits ----
    split_kernel<<<(BB*SS*DD/4 + 255)/256, 256>>>(x, xhi, xlo, BB*SS*DD/4);
    split_kernel<<<(BB*MM*DD/4 + 255)/256, 256>>>(m, mhi, mlo, BB*MM*DD/4);
    // weight transposes+splits: W[in,out] -> WT{hi,lo}[out,in]
    tsplit_kernel<<<dim3(DD/32,   DD/32, 1), dim3(32,8)>>>(Wq, WqThi, WqTlo, DD,   DD,   0, 0);
    tsplit_kernel<<<dim3(DD/32,   DD/32, 1), dim3(32,8)>>>(Wk, WkThi, WkTlo, DD,   DD,   0, 0);
    tsplit_kernel<<<dim3(DD/32,   DD/32, 1), dim3(32,8)>>>(Wv, WvThi, WvTlo, DD,   DD,   0, 0);
    tsplit_kernel<<<dim3(MLPD/32, DD/32, 1), dim3(32,8)>>>(W1, W1Thi, W1Tlo, DD,   MLPD, 0, 0);
    tsplit_kernel<<<dim3(DD/32, MLPD/32, 1), dim3(32,8)>>>(W2, W2Thi, W2Tlo, MLPD, DD,   0, 0);

    // ---- Q = x @ Wq + bq  -> split ----
    hgemm<false,true,true><<<dim3(DD/128, (BB*SS)/128, 1), 256, HG_SMEM>>>(
        xhi, xlo, WqThi, WqTlo, bq, nullptr, Qhi, Qlo,
        BB*SS, DD, DD, 0, 0, 0, 1.0f);
    // ---- K = m @ Wk + bk  -> split ----
    hgemm<false,true,true><<<dim3(DD/128, (BB*MM)/128, 1), 256, HG_SMEM>>>(
        mhi, mlo, WkThi, WkTlo, bk, nullptr, Khi, Klo,
        BB*MM, DD, DD, 0, 0, 0, 1.0f);
    // ---- V = m @ Wv + bv  -> fp32 (transposed-split next) ----
    hgemm<false,true,false><<<dim3(DD/128, (BB*MM)/128, 1), 256, HG_SMEM>>>(
        mhi, mlo, WvThi, WvTlo, bv, Vf, nullptr, nullptr,
        BB*MM, DD, DD, 0, 0, 0, 1.0f);
    // V^T per batch: [4096,512] -> [512,4096]
    tsplit_kernel<<<dim3(DD/32, MM/32, BB), dim3(32,8)>>>(
        Vf, Vthi, Vtlo, MM, DD, (long long)MM*DD, (long long)DD*MM);

    // ---- logits = scale * Q @ K^T  (fp32 to d_out) ----
    hgemm<false,false,false><<<dim3(MM/128, SS/128, BB), 256, HG_SMEM>>>(
        Qhi, Qlo, Khi, Klo, nullptr, attn, nullptr, nullptr,
        SS, MM, DD, (long long)SS*DD, (long long)MM*DD, (long long)SS*MM, scale);

    // ---- softmax (fp32 in-place) + split probabilities ----
    softmax_split<<<BB*SS, 256>>>(attn, Phi, Plo);

    // ---- V_bar = P @ V, K'=4096 -> split ----
    hgemm<false,false,true><<<dim3(DD/128, SS/128, BB), 256, HG_SMEM>>>(
        Phi, Plo, Vthi, Vtlo, nullptr, nullptr, Vbhi, Vblo,
        SS, DD, MM, (long long)SS*MM, (long long)DD*MM, (long long)SS*DD, 1.0f);

    // ---- h = relu(V_bar @ W1 + b1) -> split ----
    hgemm<true,true,true><<<dim3(MLPD/128, (BB*SS)/128, 1), 256, HG_SMEM>>>(
        Vbhi, Vblo, W1Thi, W1Tlo, b1, nullptr, Hhi, Hlo,
        BB*SS, MLPD, DD, 0, 0, 0, 1.0f);

    // ---- out = h @ W2 + b2 (fp32 to d_out) ----
    hgemm<false,true,false><<<dim3(DD/128, (BB*SS)/128, 1), 256, HG_SMEM>>>(
        Hhi, Hlo, W2Thi, W2Tlo, b2, out, nullptr, nullptr,
        BB*SS, DD, MLPD, 0, 0, 0, 1.0f);
}